// round 1
// baseline (speedup 1.0000x reference)
#include <cuda_runtime.h>

// Problem constants (fixed by the dataset: v, v_pred are [4, 8192, 3] fp32)
#define BATCH    4
#define NPTS     8192
#define THREADS  128
#define P        8            // x-points per thread
#define XB       (P*THREADS)  // 1024 x-points per block
#define CHUNK    1024         // y-points per block (per chunk)
#define YCHUNKS  (NPTS/CHUNK) // 8
#define XBLOCKS  (NPTS/XB)    // 8
#define TOTALX   (BATCH*NPTS) // 32768
#define NB2      128          // combine-kernel blocks (TOTALX / 256)

// Scratch (allocation-free rule: __device__ globals)
// x-major layout: g_partial[x][chunk] so the combine kernel reads 2x float4 coalesced.
__device__ float g_partial[(size_t)TOTALX * YCHUNKS];
__device__ float g_bsum[NB2];

// Kernel 1: per (x-block, y-chunk, batch): min over 1024 y of (y^2 - 2 x.y), + x^2.
__global__ __launch_bounds__(THREADS)
void chamfer_min_kernel(const float* __restrict__ v, const float* __restrict__ vp) {
    const int xb = blockIdx.x;
    const int yc = blockIdx.y;
    const int b  = blockIdx.z;
    const int tid = threadIdx.x;

    __shared__ float4 sy[CHUNK];  // (y.x, y.y, y.z, y^2) -> 16 KB

    // Stage y chunk into shared, computing y^2 on the fly.
    const float* ybase = v + (size_t)(b * NPTS + yc * CHUNK) * 3;
    for (int i = tid; i < CHUNK; i += THREADS) {
        float yx = ybase[i * 3 + 0];
        float yy = ybase[i * 3 + 1];
        float yz = ybase[i * 3 + 2];
        sy[i] = make_float4(yx, yy, yz, yx * yx + yy * yy + yz * yz);
    }

    // Load P x-points per thread; precompute -2x and x^2.
    float ax[P], ay[P], az[P], x2[P], m[P];
    const int x0 = b * NPTS + xb * XB;
    #pragma unroll
    for (int p = 0; p < P; p++) {
        int xi = x0 + p * THREADS + tid;
        float xx = vp[(size_t)xi * 3 + 0];
        float xy = vp[(size_t)xi * 3 + 1];
        float xz = vp[(size_t)xi * 3 + 2];
        ax[p] = -2.0f * xx;
        ay[p] = -2.0f * xy;
        az[p] = -2.0f * xz;
        x2[p] = xx * xx + xy * xy + xz * xz;
        m[p]  = 3.402823466e38f;
    }
    __syncthreads();

    // Main loop: per y, 1 LDS.128 + P * (3 FFMA + 1 FMNMX).
    #pragma unroll 4
    for (int j = 0; j < CHUNK; j++) {
        float4 y = sy[j];
        #pragma unroll
        for (int p = 0; p < P; p++) {
            float t = fmaf(ax[p], y.x, y.w);
            t = fmaf(ay[p], y.y, t);
            t = fmaf(az[p], y.z, t);
            m[p] = fminf(m[p], t);
        }
    }

    // Write per-chunk partial (x^2 folded in; same constant in every chunk).
    #pragma unroll
    for (int p = 0; p < P; p++) {
        int xi = x0 + p * THREADS + tid;
        g_partial[(size_t)xi * YCHUNKS + yc] = x2[p] + m[p];
    }
}

// Kernel 2: per x, min over its 8 chunk-partials; deterministic block tree-sum.
__global__ __launch_bounds__(256)
void chamfer_combine_kernel() {
    __shared__ float ssum[256];
    const int x = blockIdx.x * 256 + threadIdx.x;  // TOTALX == NB2*256 exactly
    const float4* p4 = reinterpret_cast<const float4*>(g_partial) + (size_t)x * 2;
    float4 a = p4[0];
    float4 c = p4[1];
    float mn = fminf(fminf(fminf(a.x, a.y), fminf(a.z, a.w)),
                     fminf(fminf(c.x, c.y), fminf(c.z, c.w)));
    ssum[threadIdx.x] = mn;
    __syncthreads();
    #pragma unroll
    for (int s = 128; s > 0; s >>= 1) {
        if (threadIdx.x < s) ssum[threadIdx.x] += ssum[threadIdx.x + s];
        __syncthreads();
    }
    if (threadIdx.x == 0) g_bsum[blockIdx.x] = ssum[0];
}

// Kernel 3: sum 128 block partials, divide by B*N, write the scalar output.
__global__ __launch_bounds__(NB2)
void chamfer_final_kernel(float* __restrict__ out) {
    __shared__ float s[NB2];
    s[threadIdx.x] = g_bsum[threadIdx.x];
    __syncthreads();
    #pragma unroll
    for (int st = NB2 / 2; st > 0; st >>= 1) {
        if (threadIdx.x < st) s[threadIdx.x] += s[threadIdx.x + st];
        __syncthreads();
    }
    if (threadIdx.x == 0) out[0] = s[0] / (float)TOTALX;
}

extern "C" void kernel_launch(void* const* d_in, const int* in_sizes, int n_in,
                              void* d_out, int out_size) {
    const float* v  = (const float*)d_in[0];   // target  y: [4, 8192, 3]
    const float* vp = (const float*)d_in[1];   // pred    x: [4, 8192, 3]
    float* out = (float*)d_out;

    dim3 grid1(XBLOCKS, YCHUNKS, BATCH);       // (8, 8, 4) = 256 blocks
    chamfer_min_kernel<<<grid1, THREADS>>>(v, vp);
    chamfer_combine_kernel<<<NB2, 256>>>();
    chamfer_final_kernel<<<1, NB2>>>(out);
}

// round 2
// speedup vs baseline: 1.2017x; 1.2017x over previous
#include <cuda_runtime.h>

// Problem constants (fixed: v, v_pred are [4, 8192, 3] fp32)
#define BATCH    4
#define NPTS     8192
#define THREADS  128
#define P        8            // x-points per thread
#define XB       (P*THREADS)  // 1024 x per block
#define XBLOCKS  (NPTS/XB)    // 8
#define YCHUNKS  32
#define CHUNK    (NPTS/YCHUNKS)  // 256 y per block
#define PAIRS    (CHUNK/2)       // 128 packed y-pairs
#define TOTALX   (BATCH*NPTS)    // 32768
#define NB2      128

// Scratch (allocation-free rule): x-major partials for coalesced combine reads.
__device__ float g_partial[(size_t)TOTALX * YCHUNKS];
__device__ float g_bsum[NB2];

// ---- Blackwell packed-f32x2 helpers (ptxas won't emit these from C++) ----
__device__ __forceinline__ unsigned long long pack2(float lo, float hi) {
    unsigned long long r;
    asm("mov.b64 %0, {%1, %2};" : "=l"(r) : "f"(lo), "f"(hi));
    return r;
}
__device__ __forceinline__ unsigned long long ffma2(unsigned long long a,
                                                    unsigned long long b,
                                                    unsigned long long c) {
    unsigned long long d;
    asm("fma.rn.f32x2 %0, %1, %2, %3;" : "=l"(d) : "l"(a), "l"(b), "l"(c));
    return d;
}
__device__ __forceinline__ void unpack2(unsigned long long v, float& lo, float& hi) {
    asm("mov.b64 {%0, %1}, %2;" : "=f"(lo), "=f"(hi) : "l"(v));
}

// Kernel 1: per (x-block, y-chunk, batch) compute min over 256 y of
// (y^2 - 2 x.y) using packed f32x2 over y-pairs; x^2 folded at epilogue.
__global__ __launch_bounds__(THREADS)
void chamfer_min_kernel(const float* __restrict__ v, const float* __restrict__ vp) {
    const int xb  = blockIdx.x;
    const int yc  = blockIdx.y;
    const int b   = blockIdx.z;
    const int tid = threadIdx.x;

    // sA[j] = (y0.x, y1.x, y0.y, y1.y); sB[j] = (y0.z, y1.z, y0^2, y1^2)
    __shared__ float4 sA[PAIRS];
    __shared__ float4 sB[PAIRS];

    // Stage one y-pair per thread (PAIRS == THREADS).
    {
        const float* yb = v + ((size_t)(b * NPTS + yc * CHUNK) + 2 * tid) * 3;
        float yx0 = yb[0], yy0 = yb[1], yz0 = yb[2];
        float yx1 = yb[3], yy1 = yb[4], yz1 = yb[5];
        float w0 = yx0 * yx0 + yy0 * yy0 + yz0 * yz0;
        float w1 = yx1 * yx1 + yy1 * yy1 + yz1 * yz1;
        sA[tid] = make_float4(yx0, yx1, yy0, yy1);
        sB[tid] = make_float4(yz0, yz1, w0, w1);
    }

    // Load P x-points; duplicate -2x into both packed halves (setup only).
    unsigned long long ax2[P], ay2[P], az2[P];
    float x2[P], m[P];
    const int x0 = b * NPTS + xb * XB;
    #pragma unroll
    for (int p = 0; p < P; p++) {
        int xi = x0 + p * THREADS + tid;
        float xx = vp[(size_t)xi * 3 + 0];
        float xy = vp[(size_t)xi * 3 + 1];
        float xz = vp[(size_t)xi * 3 + 2];
        ax2[p] = pack2(-2.0f * xx, -2.0f * xx);
        ay2[p] = pack2(-2.0f * xy, -2.0f * xy);
        az2[p] = pack2(-2.0f * xz, -2.0f * xz);
        x2[p]  = xx * xx + xy * xy + xz * xz;
        m[p]   = 3.402823466e38f;
    }
    __syncthreads();

    const ulonglong2* pA = reinterpret_cast<const ulonglong2*>(sA);
    const ulonglong2* pB = reinterpret_cast<const ulonglong2*>(sB);

    // Main loop: 2 y per iter, per pair-chain 3 FFMA2 + 2 FMNMX.
    #pragma unroll 2
    for (int j = 0; j < PAIRS; j++) {
        ulonglong2 A  = pA[j];   // .x = (y0.x,y1.x)  .y = (y0.y,y1.y)
        ulonglong2 Bv = pB[j];   // .x = (y0.z,y1.z)  .y = (y0^2,y1^2)
        #pragma unroll
        for (int p = 0; p < P; p++) {
            unsigned long long t = ffma2(ax2[p], A.x, Bv.y);
            t = ffma2(ay2[p], A.y, t);
            t = ffma2(az2[p], Bv.x, t);
            float lo, hi;
            unpack2(t, lo, hi);
            m[p] = fminf(m[p], fminf(lo, hi));  // also merges even/odd y streams
        }
    }

    #pragma unroll
    for (int p = 0; p < P; p++) {
        int xi = x0 + p * THREADS + tid;
        g_partial[(size_t)xi * YCHUNKS + yc] = x2[p] + m[p];
    }
}

// Kernel 2: per x, min over its 32 chunk-partials; deterministic block tree-sum.
__global__ __launch_bounds__(256)
void chamfer_combine_kernel() {
    __shared__ float ssum[256];
    const int x = blockIdx.x * 256 + threadIdx.x;  // TOTALX == NB2*256
    const float4* p4 = reinterpret_cast<const float4*>(g_partial) + (size_t)x * (YCHUNKS / 4);
    float mn = 3.402823466e38f;
    #pragma unroll
    for (int q = 0; q < YCHUNKS / 4; q++) {
        float4 a = p4[q];
        mn = fminf(mn, fminf(fminf(a.x, a.y), fminf(a.z, a.w)));
    }
    ssum[threadIdx.x] = mn;
    __syncthreads();
    #pragma unroll
    for (int s = 128; s > 0; s >>= 1) {
        if (threadIdx.x < s) ssum[threadIdx.x] += ssum[threadIdx.x + s];
        __syncthreads();
    }
    if (threadIdx.x == 0) g_bsum[blockIdx.x] = ssum[0];
}

// Kernel 3: sum 128 block partials, divide, write scalar.
__global__ __launch_bounds__(NB2)
void chamfer_final_kernel(float* __restrict__ out) {
    __shared__ float s[NB2];
    s[threadIdx.x] = g_bsum[threadIdx.x];
    __syncthreads();
    #pragma unroll
    for (int st = NB2 / 2; st > 0; st >>= 1) {
        if (threadIdx.x < st) s[threadIdx.x] += s[threadIdx.x + st];
        __syncthreads();
    }
    if (threadIdx.x == 0) out[0] = s[0] / (float)TOTALX;
}

extern "C" void kernel_launch(void* const* d_in, const int* in_sizes, int n_in,
                              void* d_out, int out_size) {
    const float* v  = (const float*)d_in[0];   // target y
    const float* vp = (const float*)d_in[1];   // pred   x
    float* out = (float*)d_out;

    dim3 grid1(XBLOCKS, YCHUNKS, BATCH);       // (8, 32, 4) = 1024 blocks
    chamfer_min_kernel<<<grid1, THREADS>>>(v, vp);
    chamfer_combine_kernel<<<NB2, 256>>>();
    chamfer_final_kernel<<<1, NB2>>>(out);
}